// round 5
// baseline (speedup 1.0000x reference)
#include <cuda_runtime.h>
#include <math.h>

// Problem constants: B=2, N=2048, C=1024, H=16, D=64, SCALE=1/8
#define M_ROWS 4096           // B*N
#define QKV_N  3072
#define CC     1024

// Scratch (device globals: allocation-guard-safe)
__device__ float g_qkv[4096 * 3072];   // [B*N, 3*C]  (q | k | v interleaved per reshape)
__device__ float g_att[4096 * 1024];   // [B*N, C]  attention output (b, n, h*D+d)

// ---------------------------------------------------------------------------
// Tiled SGEMM: C = A[MxK] * B[KxN] (+ bias).  BM=BN=128, BK=16, 256 thr, 8x8/thr
// ---------------------------------------------------------------------------
template <bool HAS_BIAS>
__global__ __launch_bounds__(256) void sgemm_kernel(
    const float* __restrict__ A, const float* __restrict__ B,
    const float* __restrict__ bias, float* __restrict__ C,
    int M, int N, int K)
{
    __shared__ float As[16][128];   // A^T tile
    __shared__ float Bs[16][128];

    const int tid = threadIdx.x;
    const int tr = tid >> 4;          // 0..15
    const int tc = tid & 15;          // 0..15
    const int rowBase = blockIdx.y * 128;
    const int colBase = blockIdx.x * 128;

    const int aRow = tid >> 2;        // 0..63
    const int aCol = (tid & 3) << 2;  // 0,4,8,12
    const int bRow = tid >> 5;        // 0..7
    const int bCol = (tid & 31) << 2; // 0..124

    const float* Ag = A + (size_t)rowBase * K;
    const float* Bg = B + colBase;

    float acc[8][8];
#pragma unroll
    for (int i = 0; i < 8; i++)
#pragma unroll
        for (int j = 0; j < 8; j++) acc[i][j] = 0.f;

    for (int k0 = 0; k0 < K; k0 += 16) {
#pragma unroll
        for (int p = 0; p < 2; p++) {
            float4 t = *(const float4*)(Ag + (size_t)(aRow + 64 * p) * K + k0 + aCol);
            As[aCol + 0][aRow + 64 * p] = t.x;
            As[aCol + 1][aRow + 64 * p] = t.y;
            As[aCol + 2][aRow + 64 * p] = t.z;
            As[aCol + 3][aRow + 64 * p] = t.w;
        }
#pragma unroll
        for (int p = 0; p < 2; p++) {
            *(float4*)&Bs[bRow + 8 * p][bCol] =
                *(const float4*)(Bg + (size_t)(k0 + bRow + 8 * p) * N + bCol);
        }
        __syncthreads();
#pragma unroll
        for (int kk = 0; kk < 16; kk++) {
            float ar[8], br[8];
            *(float4*)&ar[0] = *(float4*)&As[kk][tr * 8];
            *(float4*)&ar[4] = *(float4*)&As[kk][tr * 8 + 4];
            *(float4*)&br[0] = *(float4*)&Bs[kk][tc * 8];
            *(float4*)&br[4] = *(float4*)&Bs[kk][tc * 8 + 4];
#pragma unroll
            for (int i = 0; i < 8; i++)
#pragma unroll
                for (int j = 0; j < 8; j++)
                    acc[i][j] = fmaf(ar[i], br[j], acc[i][j]);
        }
        __syncthreads();
    }

#pragma unroll
    for (int i = 0; i < 8; i++) {
        const int row = rowBase + tr * 8 + i;
        float* Cr = C + (size_t)row * N + colBase + tc * 8;
#pragma unroll
        for (int j4 = 0; j4 < 8; j4 += 4) {
            float4 v;
            v.x = acc[i][j4 + 0]; v.y = acc[i][j4 + 1];
            v.z = acc[i][j4 + 2]; v.w = acc[i][j4 + 3];
            if (HAS_BIAS) {
                const float* bp = bias + colBase + tc * 8 + j4;
                v.x += bp[0]; v.y += bp[1]; v.z += bp[2]; v.w += bp[3];
            }
            *(float4*)(Cr + j4) = v;
        }
    }
}

// ---------------------------------------------------------------------------
// Flash attention, fp32. One block per (q-tile of 64, b*h). 256 threads,
// each owns a 4x4 strided subtile (rows ty+16r, cols tx+16c).
// smem: Qts [d][n] (scaled), KPs [d][n] for K^T then reused as P [row][col],
// Vs [n][d]. All stride 65 -> conflict-free inner-loop LDS.
// ---------------------------------------------------------------------------
#define FST 65
#define FLASH_SMEM (3 * 64 * FST * 4)

__global__ __launch_bounds__(256) void flash_kernel()
{
    extern __shared__ float sm[];
    float* Qts = sm;                 // [64][FST] : Qts[d*FST + n], pre-scaled
    float* KPs = sm + 64 * FST;      // K^T [d][n]  /  P [row][col]
    float* Vs  = sm + 2 * 64 * FST;  // V [n][d]

    const int tid = threadIdx.x;
    const int ty = tid >> 4;         // 0..15
    const int tx = tid & 15;         // 0..15
    const int qt = blockIdx.x;       // 0..31 (q tile)
    const int bh = blockIdx.y;       // 0..31
    const int b = bh >> 4, h = bh & 15;

    const float* Qg = g_qkv + (size_t)b * 2048 * 3072 + (size_t)h * 64;
    const float* Kg = Qg + 1024;
    const float* Vg = Qg + 2048;

    // Load Q tile transposed + scaled
    for (int i = tid; i < 64 * 16; i += 256) {
        int n = i & 63;
        int d4 = (i >> 6) << 2;
        float4 t = *(const float4*)(Qg + (size_t)(qt * 64 + n) * 3072 + d4);
        Qts[(d4 + 0) * FST + n] = t.x * 0.125f;
        Qts[(d4 + 1) * FST + n] = t.y * 0.125f;
        Qts[(d4 + 2) * FST + n] = t.z * 0.125f;
        Qts[(d4 + 3) * FST + n] = t.w * 0.125f;
    }

    float m[4], l[4], acc[4][4];
#pragma unroll
    for (int r = 0; r < 4; r++) {
        m[r] = -1e30f; l[r] = 0.f;
#pragma unroll
        for (int c = 0; c < 4; c++) acc[r][c] = 0.f;
    }

    for (int kt = 0; kt < 32; kt++) {
        __syncthreads();   // prev PV reads of KPs/Vs complete
        // K tile transposed
        for (int i = tid; i < 64 * 16; i += 256) {
            int n = i & 63;
            int d4 = (i >> 6) << 2;
            float4 t = *(const float4*)(Kg + (size_t)(kt * 64 + n) * 3072 + d4);
            KPs[(d4 + 0) * FST + n] = t.x;
            KPs[(d4 + 1) * FST + n] = t.y;
            KPs[(d4 + 2) * FST + n] = t.z;
            KPs[(d4 + 3) * FST + n] = t.w;
        }
        // V tile natural
        for (int i = tid; i < 64 * 16; i += 256) {
            int n = i >> 4;
            int d4 = (i & 15) << 2;
            float4 t = *(const float4*)(Vg + (size_t)(kt * 64 + n) * 3072 + d4);
            Vs[n * FST + d4 + 0] = t.x;
            Vs[n * FST + d4 + 1] = t.y;
            Vs[n * FST + d4 + 2] = t.z;
            Vs[n * FST + d4 + 3] = t.w;
        }
        __syncthreads();

        // S = (Q*SCALE) @ K^T for this tile
        float s[4][4];
#pragma unroll
        for (int r = 0; r < 4; r++)
#pragma unroll
            for (int c = 0; c < 4; c++) s[r][c] = 0.f;
#pragma unroll 8
        for (int dd = 0; dd < 64; dd++) {
            float qr[4], kr[4];
#pragma unroll
            for (int r = 0; r < 4; r++) qr[r] = Qts[dd * FST + ty + 16 * r];
#pragma unroll
            for (int c = 0; c < 4; c++) kr[c] = KPs[dd * FST + tx + 16 * c];
#pragma unroll
            for (int r = 0; r < 4; r++)
#pragma unroll
                for (int c = 0; c < 4; c++)
                    s[r][c] = fmaf(qr[r], kr[c], s[r][c]);
        }

        // Online softmax update (row groups are width-16 shuffle segments)
#pragma unroll
        for (int r = 0; r < 4; r++) {
            float mloc = fmaxf(fmaxf(s[r][0], s[r][1]), fmaxf(s[r][2], s[r][3]));
#pragma unroll
            for (int off = 8; off >= 1; off >>= 1)
                mloc = fmaxf(mloc, __shfl_xor_sync(0xffffffffu, mloc, off, 16));
            float mn = fmaxf(m[r], mloc);
            float fac = __expf(m[r] - mn);
            m[r] = mn;
            float lloc = 0.f;
#pragma unroll
            for (int c = 0; c < 4; c++) {
                s[r][c] = __expf(s[r][c] - mn);
                lloc += s[r][c];
            }
#pragma unroll
            for (int off = 8; off >= 1; off >>= 1)
                lloc += __shfl_xor_sync(0xffffffffu, lloc, off, 16);
            l[r] = l[r] * fac + lloc;
#pragma unroll
            for (int c = 0; c < 4; c++) acc[r][c] *= fac;
        }

        __syncthreads();   // all S reads of KPs done before P overwrite
#pragma unroll
        for (int r = 0; r < 4; r++)
#pragma unroll
            for (int c = 0; c < 4; c++)
                KPs[(ty + 16 * r) * FST + tx + 16 * c] = s[r][c];
        __syncthreads();   // P visible

        // acc += P @ V
#pragma unroll 8
        for (int j = 0; j < 64; j++) {
            float pr[4], vr[4];
#pragma unroll
            for (int r = 0; r < 4; r++) pr[r] = KPs[(ty + 16 * r) * FST + j];
#pragma unroll
            for (int c = 0; c < 4; c++) vr[c] = Vs[j * FST + tx + 16 * c];
#pragma unroll
            for (int r = 0; r < 4; r++)
#pragma unroll
                for (int c = 0; c < 4; c++)
                    acc[r][c] = fmaf(pr[r], vr[c], acc[r][c]);
        }
    }

    // Write O[b, n, h*D + d]
    float* Og = g_att + ((size_t)b * 2048 + (size_t)qt * 64) * 1024 + (size_t)h * 64;
#pragma unroll
    for (int r = 0; r < 4; r++) {
        int row = ty + 16 * r;
        float inv = 1.f / l[r];
#pragma unroll
        for (int c = 0; c < 4; c++)
            Og[(size_t)row * 1024 + tx + 16 * c] = acc[r][c] * inv;
    }
}

// ---------------------------------------------------------------------------
extern "C" void kernel_launch(void* const* d_in, const int* in_sizes, int n_in,
                              void* d_out, int out_size)
{
    const float* x      = (const float*)d_in[0];   // [2,2048,1024]
    const float* w_qkv  = (const float*)d_in[1];   // [1024,3072]
    const float* w_proj = (const float*)d_in[2];   // [1024,1024]
    const float* b_proj = (const float*)d_in[3];   // [1024]
    float* out = (float*)d_out;                    // [2,2048,1024]

    float *qkv, *att;
    cudaGetSymbolAddress((void**)&qkv, g_qkv);
    cudaGetSymbolAddress((void**)&att, g_att);

    // 1) QKV projection: [4096,1024] @ [1024,3072]
    sgemm_kernel<false><<<dim3(QKV_N / 128, M_ROWS / 128), 256>>>(
        x, w_qkv, nullptr, qkv, M_ROWS, QKV_N, CC);

    // 2) Flash attention over 32 q-tiles x 32 (b,h) pairs
    cudaFuncSetAttribute(flash_kernel,
                         cudaFuncAttributeMaxDynamicSharedMemorySize, FLASH_SMEM);
    flash_kernel<<<dim3(32, 32), 256, FLASH_SMEM>>>();

    // 3) Output projection + bias: [4096,1024] @ [1024,1024]
    sgemm_kernel<true><<<dim3(CC / 128, M_ROWS / 128), 256>>>(
        att, w_proj, b_proj, out, M_ROWS, CC, CC);
}

// round 7
// speedup vs baseline: 2.5585x; 2.5585x over previous
#include <cuda_runtime.h>
#include <math.h>
#include <stdint.h>

// Problem constants: B=2, N=2048, C=1024, H=16, D=64, SCALE=1/8
#define M_ROWS 4096
#define QKV_N  3072
#define CC     1024

// Scratch (device globals: allocation-guard-safe)
__device__ float g_qkv[4096 * 3072];   // [B*N, 3*C]
__device__ float g_att[4096 * 1024];   // [B*N, C]

// ---------------------------------------------------------------------------
// tf32 helpers
// ---------------------------------------------------------------------------
__device__ __forceinline__ uint32_t f2tf(float f) {
    uint32_t u;
    asm("cvt.rna.tf32.f32 %0, %1;" : "=r"(u) : "f"(f));
    return u;
}

__device__ __forceinline__ void mma8(float* d, const uint32_t* a, const uint32_t* b) {
    asm volatile(
        "mma.sync.aligned.m16n8k8.row.col.f32.tf32.tf32.f32 "
        "{%0,%1,%2,%3}, {%4,%5,%6,%7}, {%8,%9}, {%0,%1,%2,%3};"
        : "+f"(d[0]), "+f"(d[1]), "+f"(d[2]), "+f"(d[3])
        : "r"(a[0]), "r"(a[1]), "r"(a[2]), "r"(a[3]), "r"(b[0]), "r"(b[1]));
}

// ---------------------------------------------------------------------------
// TF32 GEMM: C = A[MxK] @ B[KxN] (+bias). BM=BN=128, BK=32, 256 thr (8 warps,
// 2x4 warp grid, 64x32 warp tile = 4x4 m16n8 mma tiles).
// As[k][m] stride 136, Bs[k][n] stride 136 -> conflict-free fragment LDS.
// ---------------------------------------------------------------------------
template <bool HAS_BIAS>
__global__ __launch_bounds__(256, 2) void gemm_tf32(
    const float* __restrict__ A, const float* __restrict__ B,
    const float* __restrict__ bias, float* __restrict__ C,
    int M, int N, int K)
{
    __shared__ uint32_t As[32][136];
    __shared__ uint32_t Bs[32][136];

    const int tid = threadIdx.x, lane = tid & 31, wid = tid >> 5;
    const int l4 = lane & 3, l2 = lane >> 2;
    const int wm = (wid & 1) * 64, wn = (wid >> 1) * 32;
    const int rowBase = blockIdx.y * 128, colBase = blockIdx.x * 128;

    const float* Ag = A + (size_t)rowBase * K;
    const float* Bg = B + colBase;

    float acc[4][4][4];
#pragma unroll
    for (int mt = 0; mt < 4; mt++)
#pragma unroll
        for (int nt = 0; nt < 4; nt++)
#pragma unroll
            for (int i = 0; i < 4; i++) acc[mt][nt][i] = 0.f;

    for (int k0 = 0; k0 < K; k0 += 32) {
#pragma unroll
        for (int i = 0; i < 4; i++) {
            int f = tid + 256 * i;
            int row = f >> 3, kc = (f & 7) << 2;
            float4 t = *(const float4*)(Ag + (size_t)row * K + k0 + kc);
            As[kc + 0][row] = f2tf(t.x);
            As[kc + 1][row] = f2tf(t.y);
            As[kc + 2][row] = f2tf(t.z);
            As[kc + 3][row] = f2tf(t.w);
        }
#pragma unroll
        for (int i = 0; i < 4; i++) {
            int f = tid + 256 * i;
            int kr = f >> 5, nc = (f & 31) << 2;
            float4 t = *(const float4*)(Bg + (size_t)(k0 + kr) * N + nc);
            uint4 u = make_uint4(f2tf(t.x), f2tf(t.y), f2tf(t.z), f2tf(t.w));
            *(uint4*)&Bs[kr][nc] = u;
        }
        __syncthreads();

#pragma unroll
        for (int ks = 0; ks < 32; ks += 8) {
            uint32_t af[4][4], bf[4][2];
#pragma unroll
            for (int mt = 0; mt < 4; mt++) {
                int r = wm + mt * 16 + l2;
                af[mt][0] = As[ks + l4][r];
                af[mt][1] = As[ks + l4][r + 8];
                af[mt][2] = As[ks + l4 + 4][r];
                af[mt][3] = As[ks + l4 + 4][r + 8];
            }
#pragma unroll
            for (int nt = 0; nt < 4; nt++) {
                int c = wn + nt * 8 + l2;
                bf[nt][0] = Bs[ks + l4][c];
                bf[nt][1] = Bs[ks + l4 + 4][c];
            }
#pragma unroll
            for (int mt = 0; mt < 4; mt++)
#pragma unroll
                for (int nt = 0; nt < 4; nt++)
                    mma8(acc[mt][nt], af[mt], bf[nt]);
        }
        __syncthreads();
    }

#pragma unroll
    for (int mt = 0; mt < 4; mt++) {
        int row = rowBase + wm + mt * 16 + l2;
#pragma unroll
        for (int nt = 0; nt < 4; nt++) {
            int col = colBase + wn + nt * 8 + 2 * l4;
            float bx = 0.f, by = 0.f;
            if (HAS_BIAS) { bx = bias[col]; by = bias[col + 1]; }
            float2 v0 = make_float2(acc[mt][nt][0] + bx, acc[mt][nt][1] + by);
            *(float2*)(C + (size_t)row * N + col) = v0;
            float2 v1 = make_float2(acc[mt][nt][2] + bx, acc[mt][nt][3] + by);
            *(float2*)(C + (size_t)(row + 8) * N + col) = v1;
        }
    }
}

// ---------------------------------------------------------------------------
// Flash attention, tf32 tensor cores. Block = (q-tile 128, one (b,h)).
// 256 thr = 8 warps, each warp owns 16 q rows across full kv width (64) ->
// softmax reductions stay inside width-4 shuffle segments.
// smem (tf32 bits): Qs[d][q] s136, Ks[d][kv] s72, Vs[kv][d] s72, Ps[q][kv] s68.
// ---------------------------------------------------------------------------
struct FlashSmem {
    uint32_t Qs[64][136];   // A-layout for S = Q@K^T
    uint32_t Ks[64][72];    // B-layout (K^T)
    uint32_t Vs[64][72];    // B-layout for P@V
    uint32_t Ps[128][68];   // A-layout for P@V
};
#define FLASH_SMEM ((int)sizeof(FlashSmem))

__global__ __launch_bounds__(256, 1) void flash_tf32()
{
    extern __shared__ uint8_t smraw[];
    FlashSmem& S = *reinterpret_cast<FlashSmem*>(smraw);

    const int tid = threadIdx.x, lane = tid & 31, wid = tid >> 5;
    const int l4 = lane & 3, l2 = lane >> 2;
    const int qt = blockIdx.x;            // 0..15 (q tile of 128)
    const int bh = blockIdx.y;            // 0..31
    const int b = bh >> 4, h = bh & 15;
    const int rowb = wid * 16;

    const float* Qg = g_qkv + (size_t)b * 2048 * 3072 + (size_t)h * 64;
    const float* Kg = Qg + 1024;
    const float* Vg = Qg + 2048;

    // Q tile (128x64) -> transposed, pre-scaled, tf32
#pragma unroll
    for (int i = 0; i < 8; i++) {
        int f = tid + 256 * i;
        int row = f >> 4, dc = (f & 15) << 2;
        float4 t = *(const float4*)(Qg + (size_t)(qt * 128 + row) * 3072 + dc);
        S.Qs[dc + 0][row] = f2tf(t.x * 0.125f);
        S.Qs[dc + 1][row] = f2tf(t.y * 0.125f);
        S.Qs[dc + 2][row] = f2tf(t.z * 0.125f);
        S.Qs[dc + 3][row] = f2tf(t.w * 0.125f);
    }

    float o[8][4];
    float m[2] = {-1e30f, -1e30f}, l[2] = {0.f, 0.f};
#pragma unroll
    for (int nt = 0; nt < 8; nt++)
#pragma unroll
        for (int i = 0; i < 4; i++) o[nt][i] = 0.f;

    for (int kt = 0; kt < 32; kt++) {
        __syncthreads();   // prior reads of Ks/Vs done
#pragma unroll
        for (int i = 0; i < 4; i++) {
            int f = tid + 256 * i;
            int r = f >> 4, dc = (f & 15) << 2;
            float4 t = *(const float4*)(Kg + (size_t)(kt * 64 + r) * 3072 + dc);
            S.Ks[dc + 0][r] = f2tf(t.x);
            S.Ks[dc + 1][r] = f2tf(t.y);
            S.Ks[dc + 2][r] = f2tf(t.z);
            S.Ks[dc + 3][r] = f2tf(t.w);
            float4 u = *(const float4*)(Vg + (size_t)(kt * 64 + r) * 3072 + dc);
            uint4 uu = make_uint4(f2tf(u.x), f2tf(u.y), f2tf(u.z), f2tf(u.w));
            *(uint4*)&S.Vs[r][dc] = uu;
        }
        __syncthreads();

        // S = Qs @ Ks : warp computes 16 x 64 (8 n-tiles), k = 64
        float s[8][4];
#pragma unroll
        for (int nt = 0; nt < 8; nt++)
#pragma unroll
            for (int i = 0; i < 4; i++) s[nt][i] = 0.f;
#pragma unroll
        for (int ks = 0; ks < 64; ks += 8) {
            uint32_t a[4];
            a[0] = S.Qs[ks + l4][rowb + l2];
            a[1] = S.Qs[ks + l4][rowb + l2 + 8];
            a[2] = S.Qs[ks + l4 + 4][rowb + l2];
            a[3] = S.Qs[ks + l4 + 4][rowb + l2 + 8];
#pragma unroll
            for (int nt = 0; nt < 8; nt++) {
                uint32_t bf[2] = {S.Ks[ks + l4][nt * 8 + l2],
                                  S.Ks[ks + l4 + 4][nt * 8 + l2]};
                mma8(s[nt], a, bf);
            }
        }

        // online softmax (rows rr=0: regs 0,1; rr=1: regs 2,3)
#pragma unroll
        for (int rr = 0; rr < 2; rr++) {
            float mloc = -1e30f;
#pragma unroll
            for (int nt = 0; nt < 8; nt++)
                mloc = fmaxf(mloc, fmaxf(s[nt][2 * rr], s[nt][2 * rr + 1]));
            mloc = fmaxf(mloc, __shfl_xor_sync(0xffffffffu, mloc, 1, 4));
            mloc = fmaxf(mloc, __shfl_xor_sync(0xffffffffu, mloc, 2, 4));
            float mn = fmaxf(m[rr], mloc);
            float fac = __expf(m[rr] - mn);
            m[rr] = mn;
            float lloc = 0.f;
#pragma unroll
            for (int nt = 0; nt < 8; nt++) {
                s[nt][2 * rr]     = __expf(s[nt][2 * rr] - mn);
                s[nt][2 * rr + 1] = __expf(s[nt][2 * rr + 1] - mn);
                lloc += s[nt][2 * rr] + s[nt][2 * rr + 1];
            }
            lloc += __shfl_xor_sync(0xffffffffu, lloc, 1, 4);
            lloc += __shfl_xor_sync(0xffffffffu, lloc, 2, 4);
            l[rr] = l[rr] * fac + lloc;
#pragma unroll
            for (int nt = 0; nt < 8; nt++) {
                o[nt][2 * rr]     *= fac;
                o[nt][2 * rr + 1] *= fac;
            }
        }

        // P -> smem (tf32), warp-private rows only
#pragma unroll
        for (int nt = 0; nt < 8; nt++) {
            int col = nt * 8 + 2 * l4;
            uint2 p0 = make_uint2(f2tf(s[nt][0]), f2tf(s[nt][1]));
            *(uint2*)&S.Ps[rowb + l2][col] = p0;
            uint2 p1 = make_uint2(f2tf(s[nt][2]), f2tf(s[nt][3]));
            *(uint2*)&S.Ps[rowb + l2 + 8][col] = p1;
        }
        __syncwarp();

        // O += P @ V : 16 x 64, k = 64
#pragma unroll
        for (int ks = 0; ks < 64; ks += 8) {
            uint32_t a[4];
            a[0] = S.Ps[rowb + l2][ks + l4];
            a[1] = S.Ps[rowb + l2 + 8][ks + l4];
            a[2] = S.Ps[rowb + l2][ks + l4 + 4];
            a[3] = S.Ps[rowb + l2 + 8][ks + l4 + 4];
#pragma unroll
            for (int nt = 0; nt < 8; nt++) {
                uint32_t bf[2] = {S.Vs[ks + l4][nt * 8 + l2],
                                  S.Vs[ks + l4 + 4][nt * 8 + l2]};
                mma8(o[nt], a, bf);
            }
        }
    }

    // epilogue: O[b, qt*128+row, h*64+d] = o / l
    const float inv0 = 1.f / l[0], inv1 = 1.f / l[1];
    float* Og = g_att + ((size_t)b * 2048 + (size_t)qt * 128) * 1024 + (size_t)h * 64;
    const int r0 = rowb + l2;
#pragma unroll
    for (int nt = 0; nt < 8; nt++) {
        int col = nt * 8 + 2 * l4;
        float2 v0 = make_float2(o[nt][0] * inv0, o[nt][1] * inv0);
        *(float2*)(Og + (size_t)r0 * 1024 + col) = v0;
        float2 v1 = make_float2(o[nt][2] * inv1, o[nt][3] * inv1);
        *(float2*)(Og + (size_t)(r0 + 8) * 1024 + col) = v1;
    }
}

// ---------------------------------------------------------------------------
extern "C" void kernel_launch(void* const* d_in, const int* in_sizes, int n_in,
                              void* d_out, int out_size)
{
    const float* x      = (const float*)d_in[0];   // [2,2048,1024]
    const float* w_qkv  = (const float*)d_in[1];   // [1024,3072]
    const float* w_proj = (const float*)d_in[2];   // [1024,1024]
    const float* b_proj = (const float*)d_in[3];   // [1024]
    float* out = (float*)d_out;                    // [2,2048,1024]

    float *qkv, *att;
    cudaGetSymbolAddress((void**)&qkv, g_qkv);
    cudaGetSymbolAddress((void**)&att, g_att);

    // 1) QKV projection: [4096,1024] @ [1024,3072]
    gemm_tf32<false><<<dim3(QKV_N / 128, M_ROWS / 128), 256>>>(
        x, w_qkv, nullptr, qkv, M_ROWS, QKV_N, CC);

    // 2) Flash attention: 16 q-tiles x 32 (b,h)
    cudaFuncSetAttribute(flash_tf32,
                         cudaFuncAttributeMaxDynamicSharedMemorySize, FLASH_SMEM);
    flash_tf32<<<dim3(16, 32), 256, FLASH_SMEM>>>();

    // 3) Output projection + bias: [4096,1024] @ [1024,1024]
    gemm_tf32<true><<<dim3(CC / 128, M_ROWS / 128), 256>>>(
        att, w_proj, b_proj, out, M_ROWS, CC, CC);
}

// round 9
// speedup vs baseline: 3.8508x; 1.5051x over previous
#include <cuda_runtime.h>
#include <math.h>
#include <stdint.h>

// Problem constants: B=2, N=2048, C=1024, H=16, D=64, SCALE=1/8
#define M_ROWS 4096
#define QKV_N  3072
#define CC     1024

// Scratch (device globals: allocation-guard-safe)
__device__ float g_qkv[4096 * 3072];     // [B*N, 3*C] tf32-rounded (q pre-scaled)
__device__ float g_att[4096 * 1024];     // [B*N, C]   tf32-rounded
__device__ float g_xr[4096 * 1024];      // tf32-rounded x
__device__ float g_wqkvr[1024 * 3072];   // tf32-rounded w_qkv
__device__ float g_wprojr[1024 * 1024];  // tf32-rounded w_proj

// ---------------------------------------------------------------------------
// helpers
// ---------------------------------------------------------------------------
__device__ __forceinline__ uint32_t f2tf(float f) {
    uint32_t u;
    asm("cvt.rna.tf32.f32 %0, %1;" : "=r"(u) : "f"(f));
    return u;
}
__device__ __forceinline__ float rtf(float f) { return __uint_as_float(f2tf(f)); }

__device__ __forceinline__ void mma8(float* d, const uint32_t* a, const uint32_t* b) {
    asm volatile(
        "mma.sync.aligned.m16n8k8.row.col.f32.tf32.tf32.f32 "
        "{%0,%1,%2,%3}, {%4,%5,%6,%7}, {%8,%9}, {%0,%1,%2,%3};"
        : "+f"(d[0]), "+f"(d[1]), "+f"(d[2]), "+f"(d[3])
        : "r"(a[0]), "r"(a[1]), "r"(a[2]), "r"(a[3]), "r"(b[0]), "r"(b[1]));
}

__device__ __forceinline__ uint32_t smaddr(const void* p) {
    return (uint32_t)__cvta_generic_to_shared(p);
}
#define CP16(dst, src) \
    asm volatile("cp.async.cg.shared.global [%0], [%1], 16;" :: "r"(dst), "l"(src))
#define CP_COMMIT() asm volatile("cp.async.commit_group;")
#define CP_WAIT(n)  asm volatile("cp.async.wait_group %0;" :: "n"(n))

__device__ __forceinline__ uint32_t fbits(float f) { return __float_as_uint(f); }

// ---------------------------------------------------------------------------
// Pre-round fp32 -> tf32-valid fp32 (vectorized)
// ---------------------------------------------------------------------------
__global__ void round_kernel(const float4* __restrict__ src, float4* __restrict__ dst, int n4) {
    int i = blockIdx.x * blockDim.x + threadIdx.x;
    if (i < n4) {
        float4 t = src[i];
        t.x = rtf(t.x); t.y = rtf(t.y); t.z = rtf(t.z); t.w = rtf(t.w);
        dst[i] = t;
    }
}

// ---------------------------------------------------------------------------
// TF32 GEMM, cp.async double-buffered. BM=BN=128, BK=32, 256 thr, 8 warps
// (2m x 4n), warp tile 64x32. As[m][36] (pad->bank 4l2+l4), Bs[k][136].
// Inputs pre-rounded: no cvt anywhere in the loop.
// ---------------------------------------------------------------------------
struct GemmSmem {
    float As[2][128][36];
    float Bs[2][32][136];
};
#define GEMM_SMEM ((int)sizeof(GemmSmem))

template <bool HAS_BIAS, bool ROUND_OUT, bool SCALE_Q>
__global__ __launch_bounds__(256, 2) void gemm_tf32(
    const float* __restrict__ A, const float* __restrict__ B,
    const float* __restrict__ bias, float* __restrict__ C,
    int M, int N, int K)
{
    extern __shared__ uint8_t smraw[];
    GemmSmem& S = *reinterpret_cast<GemmSmem*>(smraw);

    const int tid = threadIdx.x, lane = tid & 31, wid = tid >> 5;
    const int l4 = lane & 3, l2 = lane >> 2;
    const int wm = (wid & 1) * 64, wn = (wid >> 1) * 32;
    const int rowBase = blockIdx.y * 128, colBase = blockIdx.x * 128;

    const float* Ag = A + (size_t)rowBase * K;
    const float* Bg = B + colBase;

    float acc[4][4][4];
#pragma unroll
    for (int mt = 0; mt < 4; mt++)
#pragma unroll
        for (int nt = 0; nt < 4; nt++)
#pragma unroll
            for (int i = 0; i < 4; i++) acc[mt][nt][i] = 0.f;

    auto issue = [&](int s, int k0) {
#pragma unroll
        for (int i = 0; i < 4; i++) {              // A tile 128x32
            int c = tid + 256 * i;
            int row = c >> 3, cc = (c & 7) << 2;
            CP16(smaddr(&S.As[s][row][cc]), Ag + (size_t)row * K + k0 + cc);
        }
#pragma unroll
        for (int i = 0; i < 4; i++) {              // B tile 32x128
            int c = tid + 256 * i;
            int kr = c >> 5, nc = (c & 31) << 2;
            CP16(smaddr(&S.Bs[s][kr][nc]), Bg + (size_t)(k0 + kr) * N + nc);
        }
    };

    const int nIter = K >> 5;
    issue(0, 0);
    CP_COMMIT();

    for (int it = 0; it < nIter; it++) {
        if (it + 1 < nIter) {
            issue((it + 1) & 1, (it + 1) << 5);
            CP_COMMIT();
            CP_WAIT(1);
        } else {
            CP_WAIT(0);
        }
        __syncthreads();
        const int buf = it & 1;

#pragma unroll
        for (int ks = 0; ks < 32; ks += 8) {
            uint32_t af[4][4], bf[4][2];
#pragma unroll
            for (int mt = 0; mt < 4; mt++) {
                int r = wm + mt * 16 + l2;
                af[mt][0] = fbits(S.As[buf][r][ks + l4]);
                af[mt][1] = fbits(S.As[buf][r + 8][ks + l4]);
                af[mt][2] = fbits(S.As[buf][r][ks + l4 + 4]);
                af[mt][3] = fbits(S.As[buf][r + 8][ks + l4 + 4]);
            }
#pragma unroll
            for (int nt = 0; nt < 4; nt++) {
                int c = wn + nt * 8 + l2;
                bf[nt][0] = fbits(S.Bs[buf][ks + l4][c]);
                bf[nt][1] = fbits(S.Bs[buf][ks + l4 + 4][c]);
            }
#pragma unroll
            for (int mt = 0; mt < 4; mt++)
#pragma unroll
                for (int nt = 0; nt < 4; nt++)
                    mma8(acc[mt][nt], af[mt], bf[nt]);
        }
        __syncthreads();
    }

#pragma unroll
    for (int mt = 0; mt < 4; mt++) {
        int row = rowBase + wm + mt * 16 + l2;
#pragma unroll
        for (int nt = 0; nt < 4; nt++) {
            int col = colBase + wn + nt * 8 + 2 * l4;
            float sc = 1.f;
            if (SCALE_Q) sc = (col < 1024) ? 0.125f : 1.f;
            float bx = 0.f, by = 0.f;
            if (HAS_BIAS) { bx = bias[col]; by = bias[col + 1]; }
            float2 v0, v1;
            v0.x = acc[mt][nt][0] * sc + bx;  v0.y = acc[mt][nt][1] * sc + by;
            v1.x = acc[mt][nt][2] * sc + bx;  v1.y = acc[mt][nt][3] * sc + by;
            if (ROUND_OUT) {
                v0.x = rtf(v0.x); v0.y = rtf(v0.y);
                v1.x = rtf(v1.x); v1.y = rtf(v1.y);
            }
            *(float2*)(C + (size_t)row * N + col) = v0;
            *(float2*)(C + (size_t)(row + 8) * N + col) = v1;
        }
    }
}

// ---------------------------------------------------------------------------
// Flash attention, tf32 mma, cp.async double-buffered K/V.
// Block = (q-tile 128, (b,h)). 8 warps x 16 q-rows, full kv width.
// Natural layouts (cp.async, no transpose): Qs[q][68], Ks[2][kv][68],
// Vs[2][kv][72], Ps[q][68]. All fragment LDS conflict-free.
// ---------------------------------------------------------------------------
struct FlashSmem {
    float Qs[128][68];
    float Ks[2][64][68];
    float Vs[2][64][72];
    float Ps[128][68];
};
#define FLASH_SMEM ((int)sizeof(FlashSmem))

__global__ __launch_bounds__(256, 1) void flash_tf32()
{
    extern __shared__ uint8_t smraw[];
    FlashSmem& S = *reinterpret_cast<FlashSmem*>(smraw);

    const int tid = threadIdx.x, lane = tid & 31, wid = tid >> 5;
    const int l4 = lane & 3, l2 = lane >> 2;
    const int qt = blockIdx.x;            // 0..15
    const int bh = blockIdx.y;            // 0..31
    const int b = bh >> 4, h = bh & 15;
    const int rowb = wid * 16;

    const float* Qg = g_qkv + (size_t)b * 2048 * 3072 + (size_t)h * 64;
    const float* Kg = Qg + 1024;
    const float* Vg = Qg + 2048;

    auto issueKV = [&](int s, int kt) {
#pragma unroll
        for (int i = 0; i < 4; i++) {
            int c = tid + 256 * i;
            int r = c >> 4, cc = (c & 15) << 2;
            CP16(smaddr(&S.Ks[s][r][cc]), Kg + (size_t)(kt * 64 + r) * 3072 + cc);
        }
#pragma unroll
        for (int i = 0; i < 4; i++) {
            int c = tid + 256 * i;
            int r = c >> 4, cc = (c & 15) << 2;
            CP16(smaddr(&S.Vs[s][r][cc]), Vg + (size_t)(kt * 64 + r) * 3072 + cc);
        }
    };

    // prologue: Q tile + KV stage 0 in one group
#pragma unroll
    for (int i = 0; i < 8; i++) {
        int c = tid + 256 * i;
        int r = c >> 4, cc = (c & 15) << 2;
        CP16(smaddr(&S.Qs[r][cc]), Qg + (size_t)(qt * 128 + r) * 3072 + cc);
    }
    issueKV(0, 0);
    CP_COMMIT();

    float o[8][4];
    float m[2] = {-1e30f, -1e30f}, l[2] = {0.f, 0.f};
#pragma unroll
    for (int nt = 0; nt < 8; nt++)
#pragma unroll
        for (int i = 0; i < 4; i++) o[nt][i] = 0.f;

    for (int kt = 0; kt < 32; kt++) {
        if (kt + 1 < 32) {
            issueKV((kt + 1) & 1, kt + 1);
            CP_COMMIT();
            CP_WAIT(1);
        } else {
            CP_WAIT(0);
        }
        __syncthreads();
        const int buf = kt & 1;

        // S = Q @ K^T  (16 x 64 per warp, k=64). Q pre-scaled by 1/8.
        float s[8][4];
#pragma unroll
        for (int nt = 0; nt < 8; nt++)
#pragma unroll
            for (int i = 0; i < 4; i++) s[nt][i] = 0.f;
#pragma unroll
        for (int ks = 0; ks < 64; ks += 8) {
            uint32_t a[4];
            a[0] = fbits(S.Qs[rowb + l2][ks + l4]);
            a[1] = fbits(S.Qs[rowb + l2 + 8][ks + l4]);
            a[2] = fbits(S.Qs[rowb + l2][ks + l4 + 4]);
            a[3] = fbits(S.Qs[rowb + l2 + 8][ks + l4 + 4]);
#pragma unroll
            for (int nt = 0; nt < 8; nt++) {
                uint32_t bfr[2] = {fbits(S.Ks[buf][nt * 8 + l2][ks + l4]),
                                   fbits(S.Ks[buf][nt * 8 + l2][ks + l4 + 4])};
                mma8(s[nt], a, bfr);
            }
        }

        // online softmax (width-4 shuffle segments)
#pragma unroll
        for (int rr = 0; rr < 2; rr++) {
            float mloc = -1e30f;
#pragma unroll
            for (int nt = 0; nt < 8; nt++)
                mloc = fmaxf(mloc, fmaxf(s[nt][2 * rr], s[nt][2 * rr + 1]));
            mloc = fmaxf(mloc, __shfl_xor_sync(0xffffffffu, mloc, 1, 4));
            mloc = fmaxf(mloc, __shfl_xor_sync(0xffffffffu, mloc, 2, 4));
            float mn = fmaxf(m[rr], mloc);
            float fac = __expf(m[rr] - mn);
            m[rr] = mn;
            float lloc = 0.f;
#pragma unroll
            for (int nt = 0; nt < 8; nt++) {
                s[nt][2 * rr]     = __expf(s[nt][2 * rr] - mn);
                s[nt][2 * rr + 1] = __expf(s[nt][2 * rr + 1] - mn);
                lloc += s[nt][2 * rr] + s[nt][2 * rr + 1];
            }
            lloc += __shfl_xor_sync(0xffffffffu, lloc, 1, 4);
            lloc += __shfl_xor_sync(0xffffffffu, lloc, 2, 4);
            l[rr] = l[rr] * fac + lloc;
#pragma unroll
            for (int nt = 0; nt < 8; nt++) {
                o[nt][2 * rr]     *= fac;
                o[nt][2 * rr + 1] *= fac;
            }
        }

        // P -> smem (rounded), warp-private rows
#pragma unroll
        for (int nt = 0; nt < 8; nt++) {
            int col = nt * 8 + 2 * l4;
            float2 p0 = make_float2(rtf(s[nt][0]), rtf(s[nt][1]));
            *(float2*)&S.Ps[rowb + l2][col] = p0;
            float2 p1 = make_float2(rtf(s[nt][2]), rtf(s[nt][3]));
            *(float2*)&S.Ps[rowb + l2 + 8][col] = p1;
        }
        __syncwarp();

        // O += P @ V
#pragma unroll
        for (int ks = 0; ks < 64; ks += 8) {
            uint32_t a[4];
            a[0] = fbits(S.Ps[rowb + l2][ks + l4]);
            a[1] = fbits(S.Ps[rowb + l2 + 8][ks + l4]);
            a[2] = fbits(S.Ps[rowb + l2][ks + l4 + 4]);
            a[3] = fbits(S.Ps[rowb + l2 + 8][ks + l4 + 4]);
#pragma unroll
            for (int nt = 0; nt < 8; nt++) {
                uint32_t bfr[2] = {fbits(S.Vs[buf][ks + l4][nt * 8 + l2]),
                                   fbits(S.Vs[buf][ks + l4 + 4][nt * 8 + l2])};
                mma8(o[nt], a, bfr);
            }
        }
        __syncthreads();   // buf reads done before overwrite next iter
    }

    // epilogue: rounded for the proj GEMM's cp.async path
    const float inv0 = 1.f / l[0], inv1 = 1.f / l[1];
    float* Og = g_att + ((size_t)b * 2048 + (size_t)qt * 128) * 1024 + (size_t)h * 64;
    const int r0 = rowb + l2;
#pragma unroll
    for (int nt = 0; nt < 8; nt++) {
        int col = nt * 8 + 2 * l4;
        float2 v0 = make_float2(rtf(o[nt][0] * inv0), rtf(o[nt][1] * inv0));
        *(float2*)(Og + (size_t)r0 * 1024 + col) = v0;
        float2 v1 = make_float2(rtf(o[nt][2] * inv1), rtf(o[nt][3] * inv1));
        *(float2*)(Og + (size_t)(r0 + 8) * 1024 + col) = v1;
    }
}

// ---------------------------------------------------------------------------
extern "C" void kernel_launch(void* const* d_in, const int* in_sizes, int n_in,
                              void* d_out, int out_size)
{
    const float* x      = (const float*)d_in[0];   // [2,2048,1024]
    const float* w_qkv  = (const float*)d_in[1];   // [1024,3072]
    const float* w_proj = (const float*)d_in[2];   // [1024,1024]
    const float* b_proj = (const float*)d_in[3];   // [1024]
    float* out = (float*)d_out;                    // [2,2048,1024]

    float *qkv, *att, *xr, *wqkvr, *wprojr;
    cudaGetSymbolAddress((void**)&qkv, g_qkv);
    cudaGetSymbolAddress((void**)&att, g_att);
    cudaGetSymbolAddress((void**)&xr, g_xr);
    cudaGetSymbolAddress((void**)&wqkvr, g_wqkvr);
    cudaGetSymbolAddress((void**)&wprojr, g_wprojr);

    // 0) pre-round inputs to tf32 grid (removes all cvt from GEMM hot loops)
    round_kernel<<<(4096 * 1024 / 4 + 255) / 256, 256>>>((const float4*)x, (float4*)xr, 4096 * 1024 / 4);
    round_kernel<<<(1024 * 3072 / 4 + 255) / 256, 256>>>((const float4*)w_qkv, (float4*)wqkvr, 1024 * 3072 / 4);
    round_kernel<<<(1024 * 1024 / 4 + 255) / 256, 256>>>((const float4*)w_proj, (float4*)wprojr, 1024 * 1024 / 4);

    // 1) QKV projection (epilogue: scale q by 1/8, round to tf32)
    cudaFuncSetAttribute((const void*)gemm_tf32<false, true, true>,
                         cudaFuncAttributeMaxDynamicSharedMemorySize, GEMM_SMEM);
    gemm_tf32<false, true, true><<<dim3(QKV_N / 128, M_ROWS / 128), 256, GEMM_SMEM>>>(
        xr, wqkvr, nullptr, qkv, M_ROWS, QKV_N, CC);

    // 2) Flash attention
    cudaFuncSetAttribute(flash_tf32,
                         cudaFuncAttributeMaxDynamicSharedMemorySize, FLASH_SMEM);
    flash_tf32<<<dim3(16, 32), 256, FLASH_SMEM>>>();

    // 3) Output projection + bias (full fp32 out)
    cudaFuncSetAttribute((const void*)gemm_tf32<true, false, false>,
                         cudaFuncAttributeMaxDynamicSharedMemorySize, GEMM_SMEM);
    gemm_tf32<true, false, false><<<dim3(CC / 128, M_ROWS / 128), 256, GEMM_SMEM>>>(
        att, wprojr, b_proj, out, M_ROWS, CC, CC);
}